// round 3
// baseline (speedup 1.0000x reference)
#include <cuda_runtime.h>
#include <cuda_bf16.h>

// Dynamic relative-position-bias table: [head][idx], idx = di*15+dj, 6*225
__device__ float g_rpb[6 * 225];

// ---------------- packed f32x2 helpers (FFMA2 path, sm_100+) ----------------
static __device__ __forceinline__ unsigned long long pk2(float a, float b) {
    unsigned long long r;
    asm("mov.b64 %0, {%1,%2};" : "=l"(r) : "f"(a), "f"(b));
    return r;
}
static __device__ __forceinline__ void upk2(unsigned long long p, float &a, float &b) {
    asm("mov.b64 {%0,%1}, %2;" : "=f"(a), "=f"(b) : "l"(p));
}
static __device__ __forceinline__ void fma2(unsigned long long &d,
                                            unsigned long long a,
                                            unsigned long long b) {
    asm("fma.rn.f32x2 %0, %1, %2, %0;" : "+l"(d) : "l"(a), "l"(b));
}
static __device__ __forceinline__ unsigned long long add2(unsigned long long a,
                                                          unsigned long long b) {
    unsigned long long r;
    asm("add.rn.f32x2 %0, %1, %2;" : "=l"(r) : "l"(a), "l"(b));
    return r;
}

// ---------------- RPE MLP kernel: 225 rows, fully thread-local ----------------
static __device__ __forceinline__ void ln_relu12(float *x, const float *g, const float *b) {
    float m = 0.f;
#pragma unroll
    for (int j = 0; j < 12; j++) m += x[j];
    m *= (1.0f / 12.0f);
    float v = 0.f;
#pragma unroll
    for (int j = 0; j < 12; j++) { float d = x[j] - m; v += d * d; }
    v *= (1.0f / 12.0f);
    float inv = rsqrtf(v + 1e-5f);
#pragma unroll
    for (int j = 0; j < 12; j++) {
        float t = (x[j] - m) * inv * g[j] + b[j];
        x[j] = fmaxf(t, 0.f);
    }
}

__global__ void rpe_mlp_kernel(const float *__restrict__ w_proj, const float *__restrict__ b_proj,
                               const float *__restrict__ ln1_g, const float *__restrict__ ln1_b,
                               const float *__restrict__ w1,    const float *__restrict__ b1,
                               const float *__restrict__ ln2_g, const float *__restrict__ ln2_b,
                               const float *__restrict__ w2,    const float *__restrict__ b2,
                               const float *__restrict__ ln3_g, const float *__restrict__ ln3_b,
                               const float *__restrict__ w3,    const float *__restrict__ b3) {
    int r = threadIdx.x;
    if (r >= 225) return;
    float in0 = (float)(r / 15 - 7);   // bh = i - (HS-1)
    float in1 = (float)(r % 15 - 7);   // bw
    float x[12], y[12];
#pragma unroll
    for (int j = 0; j < 12; j++)
        x[j] = in0 * w_proj[j] + in1 * w_proj[12 + j] + b_proj[j];
    ln_relu12(x, ln1_g, ln1_b);
#pragma unroll
    for (int j = 0; j < 12; j++) {
        float acc = b1[j];
#pragma unroll
        for (int i = 0; i < 12; i++) acc += x[i] * w1[i * 12 + j];
        y[j] = acc;
    }
    ln_relu12(y, ln2_g, ln2_b);
#pragma unroll
    for (int j = 0; j < 12; j++) {
        float acc = b2[j];
#pragma unroll
        for (int i = 0; i < 12; i++) acc += y[i] * w2[i * 12 + j];
        x[j] = acc;
    }
    ln_relu12(x, ln3_g, ln3_b);
#pragma unroll
    for (int h = 0; h < 6; h++) {
        float acc = b3[h];
#pragma unroll
        for (int i = 0; i < 12; i++) acc += x[i] * w3[i * 6 + h];
        g_rpb[h * 225 + r] = acc;
    }
}

// ---------------- windowed attention kernel ----------------
// grid.x = B * (H/8) * (W/8) * NH = 4*32*32*6 = 24576 ; block = 64 threads
// CTA = one (window, head). Thread = one query row (n = 0..63).
#define QK_SCALE 0.17677669529663687f  // 32^-0.5

__global__ __launch_bounds__(64) void attn_kernel(const float *__restrict__ Q,
                                                  const float *__restrict__ K,
                                                  const float *__restrict__ V,
                                                  float *__restrict__ O) {
    __shared__ __align__(16) float sk[64][32];
    __shared__ __align__(16) float sv[64][32];
    __shared__ float sq[64][33];   // padded: conflict-free row reads/writes
    __shared__ float srpb[232];

    int head = blockIdx.x % 6;
    int win  = blockIdx.x / 6;
    int b    = win >> 10;          // 1024 windows per image
    int whb  = (win >> 5) & 31;
    int wwb  = win & 31;
    int tid = threadIdx.x, lane = tid & 31, wp = tid >> 5;

    for (int i = tid; i < 225; i += 64) srpb[i] = g_rpb[head * 225 + i];

    long base = (((long)b) << 16) * 192 + head * 32;  // b*L*C + head*hd
    int r0 = whb << 3, c0 = wwb << 3;
    for (int p = wp; p < 64; p += 2) {
        int rr = r0 + (p >> 3), cc = c0 + (p & 7);
        long g = base + (long)(rr * 256 + cc) * 192 + lane;
        sq[p][lane] = Q[g] * QK_SCALE;
        sk[p][lane] = K[g];
        sv[p][lane] = V[g];
    }
    __syncthreads();

    const int n = tid;
    unsigned long long qp[16];
#pragma unroll
    for (int i = 0; i < 16; i++) qp[i] = pk2(sq[n][2 * i], sq[n][2 * i + 1]);
    const int i1 = n >> 3, j1 = n & 7;

    // ---- S = q·kT + rpb, row n in registers ----
    float s[64];
#pragma unroll
    for (int m = 0; m < 64; m++) {
        const ulonglong2 *kr = reinterpret_cast<const ulonglong2 *>(sk[m]);
        unsigned long long a0 = 0ull, a1 = 0ull;
#pragma unroll
        for (int j = 0; j < 8; j++) {
            ulonglong2 kk = kr[j];         // 4 k-floats, broadcast (conflict-free)
            fma2(a0, qp[2 * j],     kk.x);
            fma2(a1, qp[2 * j + 1], kk.y);
        }
        unsigned long long at = add2(a0, a1);
        float lo, hi; upk2(at, lo, hi);
        int di = i1 - (m >> 3) + 7;
        int dj = j1 - (m & 7) + 7;
        s[m] = lo + hi + srpb[di * 15 + dj];
    }

    // ---- softmax over m (exact fp32) ----
    float mx = s[0];
#pragma unroll
    for (int m = 1; m < 64; m++) mx = fmaxf(mx, s[m]);
    float sum = 0.f;
#pragma unroll
    for (int m = 0; m < 64; m++) { float e = __expf(s[m] - mx); s[m] = e; sum += e; }
    float inv = 1.0f / sum;

    // ---- O = P · V ----
    unsigned long long acc[16];
#pragma unroll
    for (int i = 0; i < 16; i++) acc[i] = 0ull;
#pragma unroll
    for (int m = 0; m < 64; m++) {
        unsigned long long pm = pk2(s[m], s[m]);
        const ulonglong2 *vr = reinterpret_cast<const ulonglong2 *>(sv[m]);
#pragma unroll
        for (int j = 0; j < 8; j++) {
            ulonglong2 vv = vr[j];
            fma2(acc[2 * j],     pm, vv.x);
            fma2(acc[2 * j + 1], pm, vv.y);
        }
    }

    // stage output through sq for coalesced global stores
    __syncthreads();
#pragma unroll
    for (int i = 0; i < 16; i++) {
        float a, bb; upk2(acc[i], a, bb);
        sq[n][2 * i]     = a * inv;
        sq[n][2 * i + 1] = bb * inv;
    }
    __syncthreads();
    for (int p = wp; p < 64; p += 2) {
        int rr = r0 + (p >> 3), cc = c0 + (p & 7);
        long g = base + (long)(rr * 256 + cc) * 192 + lane;
        O[g] = sq[p][lane];
    }
}

// ---------------- launch ----------------
extern "C" void kernel_launch(void *const *d_in, const int *in_sizes, int n_in,
                              void *d_out, int out_size) {
    const float *q = (const float *)d_in[0];
    const float *k = (const float *)d_in[1];
    const float *v = (const float *)d_in[2];
    // d_in[3]=H, d_in[4]=W (int32, fixed 256x256 for this problem)
    const float *w_proj = (const float *)d_in[5];
    const float *b_proj = (const float *)d_in[6];
    const float *ln1_g  = (const float *)d_in[7];
    const float *ln1_b  = (const float *)d_in[8];
    const float *w1     = (const float *)d_in[9];
    const float *b1     = (const float *)d_in[10];
    const float *ln2_g  = (const float *)d_in[11];
    const float *ln2_b  = (const float *)d_in[12];
    const float *w2     = (const float *)d_in[13];
    const float *b2     = (const float *)d_in[14];
    const float *ln3_g  = (const float *)d_in[15];
    const float *ln3_b  = (const float *)d_in[16];
    const float *w3     = (const float *)d_in[17];
    const float *b3     = (const float *)d_in[18];
    float *out = (float *)d_out;

    rpe_mlp_kernel<<<1, 256>>>(w_proj, b_proj, ln1_g, ln1_b, w1, b1,
                               ln2_g, ln2_b, w2, b2, ln3_g, ln3_b, w3, b3);

    // B=4, H=W=256 -> 4*32*32 windows * 6 heads
    attn_kernel<<<24576, 64>>>(q, k, v, out);
}